// round 1
// baseline (speedup 1.0000x reference)
#include <cuda_runtime.h>
#include <cuda_bf16.h>

// Problem dims (fixed by reference setup_inputs)
#define B_  4
#define N_  32
#define R_  64
#define H_  480
#define W_  640
#define HW_ (H_ * W_)          // 307200
#define NVEC (HW_ / 4)         // 76800 float4 per (b,n) slice
#define BN_ (B_ * N_)          // 128
#define BR_ (B_ * R_)          // 256

#define MARGIN_RANK 0.1f
#define MARGIN_OCC  0.3f
#define LAMBDA_OCC  1.5f
#define MIN_PIXELS  20.0f

// Scratch: per-(b,n) sum of masked depth and mask count
__device__ float g_sum[BN_];
__device__ float g_cnt[BN_];

__global__ void zero_kernel() {
    int t = threadIdx.x;
    if (t < BN_) { g_sum[t] = 0.0f; g_cnt[t] = 0.0f; }
}

__global__ void __launch_bounds__(256) reduce_kernel(
    const float* __restrict__ depth,   // [B,1,H,W]
    const float* __restrict__ masks)   // [B,N,H,W]
{
    const int bn = blockIdx.y;           // 0..127
    const int b  = bn >> 5;              // N_ = 32
    const float4* __restrict__ mp = reinterpret_cast<const float4*>(masks) + (size_t)bn * NVEC;
    const float4* __restrict__ dp = reinterpret_cast<const float4*>(depth) + (size_t)b  * NVEC;

    float s = 0.0f, c = 0.0f;
    const int stride = gridDim.x * blockDim.x;
    for (int i = blockIdx.x * blockDim.x + threadIdx.x; i < NVEC; i += stride) {
        float4 m = mp[i];
        float4 d = dp[i];
        if (m.x > 0.5f) { s += d.x; c += 1.0f; }
        if (m.y > 0.5f) { s += d.y; c += 1.0f; }
        if (m.z > 0.5f) { s += d.z; c += 1.0f; }
        if (m.w > 0.5f) { s += d.w; c += 1.0f; }
    }

    // warp reduce
    #pragma unroll
    for (int off = 16; off > 0; off >>= 1) {
        s += __shfl_xor_sync(0xFFFFFFFFu, s, off);
        c += __shfl_xor_sync(0xFFFFFFFFu, c, off);
    }

    __shared__ float sh_s[8], sh_c[8];
    const int lane = threadIdx.x & 31;
    const int wid  = threadIdx.x >> 5;
    if (lane == 0) { sh_s[wid] = s; sh_c[wid] = c; }
    __syncthreads();
    if (wid == 0) {
        s = (lane < (blockDim.x >> 5)) ? sh_s[lane] : 0.0f;
        c = (lane < (blockDim.x >> 5)) ? sh_c[lane] : 0.0f;
        #pragma unroll
        for (int off = 4; off > 0; off >>= 1) {
            s += __shfl_xor_sync(0xFFFFFFFFu, s, off);
            c += __shfl_xor_sync(0xFFFFFFFFu, c, off);
        }
        if (lane == 0) {
            atomicAdd(&g_sum[bn], s);
            atomicAdd(&g_cnt[bn], c);
        }
    }
}

__global__ void __launch_bounds__(BR_) finalize_kernel(
    const int*   __restrict__ subj,
    const int*   __restrict__ obj,
    const int*   __restrict__ rel,
    const float* __restrict__ conf,
    float* __restrict__ out)
{
    const int t = threadIdx.x;          // 0..255
    const int b = t / R_;

    const int  rt = rel[t];
    const int  si = subj[t];
    const int  oi = obj[t];
    const int  a  = (rt == 1) ? oi : si;
    const int  bb = (rt == 1) ? si : oi;

    const float cntA = g_cnt[b * N_ + a];
    const float cntB = g_cnt[b * N_ + bb];
    const float dA   = g_sum[b * N_ + a]  / fmaxf(cntA, 1.0f);
    const float dB   = g_sum[b * N_ + bb] / fmaxf(cntB, 1.0f);
    const bool  valid = (cntA >= MIN_PIXELS) && (cntB >= MIN_PIXELS);

    const float margin = (rt == 2) ? MARGIN_OCC : MARGIN_RANK;
    const float coeff  = (rt == 2) ? LAMBDA_OCC : 1.0f;
    const float viol   = fmaxf(dA - dB + margin, 0.0f);

    float total = coeff * conf[t] * (valid ? 1.0f : 0.0f) * viol;
    float count = valid ? 1.0f : 0.0f;

    // block reduce (256 threads = 8 warps)
    #pragma unroll
    for (int off = 16; off > 0; off >>= 1) {
        total += __shfl_xor_sync(0xFFFFFFFFu, total, off);
        count += __shfl_xor_sync(0xFFFFFFFFu, count, off);
    }
    __shared__ float sh_t[8], sh_n[8];
    const int lane = t & 31, wid = t >> 5;
    if (lane == 0) { sh_t[wid] = total; sh_n[wid] = count; }
    __syncthreads();
    if (t == 0) {
        float T = 0.0f, C = 0.0f;
        #pragma unroll
        for (int w = 0; w < 8; ++w) { T += sh_t[w]; C += sh_n[w]; }
        out[0] = (C > 0.0f) ? (T / fmaxf(C, 1.0f)) : 0.0f;
    }
}

extern "C" void kernel_launch(void* const* d_in, const int* in_sizes, int n_in,
                              void* d_out, int out_size)
{
    const float* depth = (const float*)d_in[0];
    const float* masks = (const float*)d_in[1];
    const int*   subj  = (const int*)  d_in[2];
    const int*   obj   = (const int*)  d_in[3];
    const int*   rel   = (const int*)  d_in[4];
    const float* conf  = (const float*)d_in[5];
    float*       out   = (float*)d_out;

    zero_kernel<<<1, 256>>>();
    reduce_kernel<<<dim3(4, BN_), 256>>>(depth, masks);
    finalize_kernel<<<1, BR_>>>(subj, obj, rel, conf, out);
}

// round 4
// speedup vs baseline: 1.6661x; 1.6661x over previous
#include <cuda_runtime.h>
#include <cuda_bf16.h>

// Problem dims (fixed by reference setup_inputs)
#define B_   4
#define N_   32
#define R_   64
#define H_   480
#define W_   640
#define HW_  (H_ * W_)         // 307200
#define NVEC (HW_ / 4)         // 76800 float4 per (b,n) slice
#define BN_  (B_ * N_)         // 128
#define BR_  (B_ * R_)         // 256

#define NGRP    8              // n-values per block
#define GROUPS  (B_ * N_ / NGRP)   // 16
#define CHUNKS  37             // pixel chunks -> 16*37 = 592 = 4*148 blocks
#define NBLOCKS (GROUPS * CHUNKS)
#define CHUNK_SZ ((NVEC + CHUNKS - 1) / CHUNKS)   // 2076

#define MARGIN_RANK 0.1f
#define MARGIN_OCC  0.3f
#define LAMBDA_OCC  1.5f
#define MIN_PIXELS  20.0f

// Per-(chunk, bn) partials — each block owns its slots, no atomics needed.
__device__ float g_ps[CHUNKS * BN_];
__device__ float g_pc[CHUNKS * BN_];

__global__ void __launch_bounds__(256) reduce_kernel(
    const float* __restrict__ depth,   // [B,1,H,W]
    const float* __restrict__ masks)   // [B,N,H,W]
{
    const int bx    = blockIdx.x;          // 0..591
    const int chunk = bx % CHUNKS;
    const int grp   = bx / CHUNKS;         // 0..15
    const int b     = grp >> 2;            // 4 groups per batch
    const int n0    = (grp & 3) * NGRP;

    const float4* __restrict__ dp = reinterpret_cast<const float4*>(depth)
                                    + (size_t)b * NVEC;
    const float4* __restrict__ mp = reinterpret_cast<const float4*>(masks)
                                    + (size_t)(b * N_ + n0) * NVEC;

    float s[NGRP], c[NGRP];
    #pragma unroll
    for (int j = 0; j < NGRP; ++j) { s[j] = 0.0f; c[j] = 0.0f; }

    const int i0 = chunk * CHUNK_SZ;
    const int i1 = min(i0 + CHUNK_SZ, NVEC);

    for (int i = i0 + threadIdx.x; i < i1; i += 256) {
        float4 d = dp[i];
        float4 m[NGRP];
        #pragma unroll
        for (int j = 0; j < NGRP; ++j)
            m[j] = mp[(size_t)j * NVEC + i];
        #pragma unroll
        for (int j = 0; j < NGRP; ++j) {
            if (m[j].x > 0.5f) { s[j] += d.x; c[j] += 1.0f; }
            if (m[j].y > 0.5f) { s[j] += d.y; c[j] += 1.0f; }
            if (m[j].z > 0.5f) { s[j] += d.z; c[j] += 1.0f; }
            if (m[j].w > 0.5f) { s[j] += d.w; c[j] += 1.0f; }
        }
    }

    // Warp-reduce all 16 accumulators
    #pragma unroll
    for (int j = 0; j < NGRP; ++j) {
        #pragma unroll
        for (int off = 16; off > 0; off >>= 1) {
            s[j] += __shfl_xor_sync(0xFFFFFFFFu, s[j], off);
            c[j] += __shfl_xor_sync(0xFFFFFFFFu, c[j], off);
        }
    }

    __shared__ float sh[8][2 * NGRP];      // [warp][16 values]
    const int lane = threadIdx.x & 31;
    const int wid  = threadIdx.x >> 5;
    if (lane == 0) {
        #pragma unroll
        for (int j = 0; j < NGRP; ++j) {
            sh[wid][j]        = s[j];
            sh[wid][NGRP + j] = c[j];
        }
    }
    __syncthreads();

    if (threadIdx.x < 2 * NGRP) {
        float v = 0.0f;
        #pragma unroll
        for (int w = 0; w < 8; ++w) v += sh[w][threadIdx.x];
        const int j    = threadIdx.x & (NGRP - 1);
        const int bn   = b * N_ + n0 + j;
        if (threadIdx.x < NGRP) g_ps[chunk * BN_ + bn] = v;
        else                    g_pc[chunk * BN_ + bn] = v;
    }
}

__global__ void __launch_bounds__(BR_) finalize_kernel(
    const int*   __restrict__ subj,
    const int*   __restrict__ obj,
    const int*   __restrict__ rel,
    const float* __restrict__ conf,
    float* __restrict__ out)
{
    __shared__ float sh_mean[BN_], sh_cnt[BN_];
    const int t = threadIdx.x;          // 0..255

    if (t < BN_) {
        float sAcc = 0.0f, cAcc = 0.0f;
        #pragma unroll
        for (int ch = 0; ch < CHUNKS; ++ch) {
            sAcc += g_ps[ch * BN_ + t];
            cAcc += g_pc[ch * BN_ + t];
        }
        sh_mean[t] = sAcc / fmaxf(cAcc, 1.0f);
        sh_cnt[t]  = cAcc;
    }
    __syncthreads();

    const int b  = t / R_;
    const int rt = rel[t];
    const int si = subj[t];
    const int oi = obj[t];
    const int a  = (rt == 1) ? oi : si;
    const int bb = (rt == 1) ? si : oi;

    const float cntA = sh_cnt[b * N_ + a];
    const float cntB = sh_cnt[b * N_ + bb];
    const float dA   = sh_mean[b * N_ + a];
    const float dB   = sh_mean[b * N_ + bb];
    const bool  valid = (cntA >= MIN_PIXELS) && (cntB >= MIN_PIXELS);

    const float margin = (rt == 2) ? MARGIN_OCC : MARGIN_RANK;
    const float coeff  = (rt == 2) ? LAMBDA_OCC : 1.0f;
    const float viol   = fmaxf(dA - dB + margin, 0.0f);

    float total = coeff * conf[t] * (valid ? 1.0f : 0.0f) * viol;
    float count = valid ? 1.0f : 0.0f;

    #pragma unroll
    for (int off = 16; off > 0; off >>= 1) {
        total += __shfl_xor_sync(0xFFFFFFFFu, total, off);
        count += __shfl_xor_sync(0xFFFFFFFFu, count, off);
    }
    __shared__ float sh_t[8], sh_n[8];
    const int lane = t & 31, wid = t >> 5;
    if (lane == 0) { sh_t[wid] = total; sh_n[wid] = count; }
    __syncthreads();
    if (t == 0) {
        float T = 0.0f, C = 0.0f;
        #pragma unroll
        for (int w = 0; w < 8; ++w) { T += sh_t[w]; C += sh_n[w]; }
        out[0] = (C > 0.0f) ? (T / fmaxf(C, 1.0f)) : 0.0f;
    }
}

extern "C" void kernel_launch(void* const* d_in, const int* in_sizes, int n_in,
                              void* d_out, int out_size)
{
    const float* depth = (const float*)d_in[0];
    const float* masks = (const float*)d_in[1];
    const int*   subj  = (const int*)  d_in[2];
    const int*   obj   = (const int*)  d_in[3];
    const int*   rel   = (const int*)  d_in[4];
    const float* conf  = (const float*)d_in[5];
    float*       out   = (float*)d_out;

    reduce_kernel<<<NBLOCKS, 256>>>(depth, masks);
    finalize_kernel<<<1, BR_>>>(subj, obj, rel, conf, out);
}